// round 15
// baseline (speedup 1.0000x reference)
#include <cuda_runtime.h>
#include <stdint.h>

#define N_NODES 50000
#define N_EDGES 800000
#define F_HID 128
#define F_OUT 40
#define NB_NODE 196   /* ceil(50000/256) */
#define E_HALF 400000
#define NB_EDGE2 1563 /* ceil(400000/256) */
#define AGG_BLOCKS 1184  /* 148 SMs * 8 blocks: single wave, grid-stride */

// ---------------- device scratch ----------------
__device__ __align__(16) int   g_row[N_EDGES];
__device__ __align__(16) int   g_col[N_EDGES];
__device__ __align__(16) float g_ewc[N_EDGES];
__device__ __align__(16) int   g_pos[N_EDGES];
__device__ __align__(16) float g_deg[N_NODES];
__device__ __align__(16) float g_dinv[N_NODES];
__device__ __align__(16) int   g_count[N_NODES];
__device__ __align__(16) int   g_mint[N_NODES];
__device__ __align__(16) int   g_rowptr[N_NODES + 1];
__device__ __align__(16) int   g_outpos[N_NODES];
__device__ volatile unsigned long long g_bsum[256];
__device__ __align__(16) int2  g_csr[N_EDGES];
__device__ __align__(16) float g_hA[(size_t)N_NODES * F_HID];
__device__ __align__(16) float g_hB[(size_t)N_NODES * F_HID];
__device__ __align__(16) float g_hC[(size_t)N_NODES * F_OUT];
__device__ int g_is64;

// ---------------- packed f32x2 helpers (Blackwell FFMA2) ----------------
__device__ __forceinline__ unsigned long long pack2(float lo, float hi) {
    unsigned long long r;
    asm("mov.b64 %0, {%1, %2};" : "=l"(r) : "f"(lo), "f"(hi));
    return r;
}
__device__ __forceinline__ void ffma2(unsigned long long& d,
                                      unsigned long long a,
                                      unsigned long long b) {
    asm("fma.rn.f32x2 %0, %1, %2, %0;" : "+l"(d) : "l"(a), "l"(b));
}
__device__ __forceinline__ float2 unpack2(unsigned long long v) {
    float lo, hi;
    asm("mov.b64 {%0, %1}, %2;" : "=f"(lo), "=f"(hi) : "l"(v));
    return make_float2(lo, hi);
}

// ---------------- fused init: probe + zero + mask decode ----------------
__global__ void k_prep0(const void* mask_, const void* ei_) {
    int i = blockIdx.x * blockDim.x + threadIdx.x;
    if (i == 0) {
        const long long* p = (const long long*)ei_;
        int ok = 1;
        #pragma unroll 1
        for (int k = 0; k < 64; ++k) {
            long long v = p[k];
            if (v < 0 || v >= N_NODES) { ok = 0; break; }
        }
        g_is64 = ok;
    }
    if (i < 256) g_bsum[i] = 0ull;
    if (i < N_NODES) {
        g_deg[i] = 0.0f;
        g_count[i] = 0;
        unsigned int w0 = ((const unsigned int*)mask_)[0];
        int m;
        if (w0 == 1u) m = (((const int*)mask_)[i] != 0) ? 1 : 0;
        else          m = (((const unsigned char*)mask_)[i] != 0) ? 1 : 0;
        g_mint[i] = m;
    }
}

// ---------------- edge prep: 2 edges/thread, batched loads ----------------
__global__ void k_edge_prep(const void* ei_, const float* __restrict__ ew) {
    int e = blockIdx.x * blockDim.x + threadIdx.x;
    if (e >= E_HALF) return;
    const int e2 = e + E_HALF;
    int r1, c1, r2, c2;
    if (g_is64) {
        const long long* ei = (const long long*)ei_;
        long long a0 = __ldg(ei + e);
        long long a1 = __ldg(ei + N_EDGES + e);
        long long a2 = __ldg(ei + e2);
        long long a3 = __ldg(ei + N_EDGES + e2);
        r1 = (int)a0; c1 = (int)a1; r2 = (int)a2; c2 = (int)a3;
    } else {
        const int* ei = (const int*)ei_;
        int a0 = __ldg(ei + e);
        int a1 = __ldg(ei + N_EDGES + e);
        int a2 = __ldg(ei + e2);
        int a3 = __ldg(ei + N_EDGES + e2);
        r1 = a0; c1 = a1; r2 = a2; c2 = a3;
    }
    float w1 = __ldg(ew + e);
    float w2 = __ldg(ew + e2);
    r1 = min(max(r1, 0), N_NODES - 1);
    c1 = min(max(c1, 0), N_NODES - 1);
    r2 = min(max(r2, 0), N_NODES - 1);
    c2 = min(max(c2, 0), N_NODES - 1);
    g_row[e] = r1;  g_col[e] = c1;  g_ewc[e] = w1;
    g_row[e2] = r2; g_col[e2] = c2; g_ewc[e2] = w2;
    atomicAdd(&g_deg[c1], w1);
    atomicAdd(&g_deg[c2], w2);
    g_pos[e]  = atomicAdd(&g_count[c1], 1);
    g_pos[e2] = atomicAdd(&g_count[c2], 1);
}

// ---------------- single-kernel dual scan (decoupled lookback) ----------------
__global__ void k_scan_fused() {
    __shared__ int sa[256], sb[256];
    __shared__ int s_prefA, s_prefB;
    const int t = threadIdx.x;
    const int bid = blockIdx.x;
    const int i = bid * 256 + t;
    int va = (i < N_NODES) ? g_count[i] : 0;
    int vb = (i < N_NODES) ? g_mint[i] : 0;
    sa[t] = va; sb[t] = vb;
    __syncthreads();
    for (int off = 1; off < 256; off <<= 1) {
        int aa = (t >= off) ? sa[t - off] : 0;
        int ab = (t >= off) ? sb[t - off] : 0;
        __syncthreads();
        sa[t] += aa; sb[t] += ab;
        __syncthreads();
    }
    if (t == 255) {
        unsigned long long v = ((unsigned long long)(unsigned)sb[255] << 32)
                             | (unsigned)(sa[255] + 1);
        g_bsum[bid] = v;
    }
    if (t < 32) {
        int pA = 0, pB = 0;
        for (int p = t; p < bid; p += 32) {
            unsigned long long v;
            do { v = g_bsum[p]; } while ((unsigned)v == 0u);
            pA += (int)((unsigned)v) - 1;
            pB += (int)(v >> 32);
        }
        #pragma unroll
        for (int off = 16; off > 0; off >>= 1) {
            pA += __shfl_down_sync(0xffffffffu, pA, off);
            pB += __shfl_down_sync(0xffffffffu, pB, off);
        }
        if (t == 0) { s_prefA = pA; s_prefB = pB; }
    }
    __syncthreads();
    if (i < N_NODES) {
        g_rowptr[i] = s_prefA + sa[t] - va;
        g_outpos[i] = s_prefB + sb[t] - vb;
        g_dinv[i] = rsqrtf(g_deg[i] + 1.0f);
    }
    if (bid == NB_NODE - 1 && t == 255) {
        g_rowptr[N_NODES] = s_prefA + sa[255];
    }
}

// ---------------- scatter: 2 edges/thread, no atomics ----------------
__global__ void k_scatter() {
    int e = blockIdx.x * blockDim.x + threadIdx.x;
    if (e >= E_HALF) return;
    const int e2 = e + E_HALF;
    int c1 = g_col[e],  r1 = g_row[e];
    int c2 = g_col[e2], r2 = g_row[e2];
    float w1 = g_ewc[e], w2 = g_ewc[e2];
    int p1 = g_pos[e],   p2 = g_pos[e2];
    int rp1 = __ldg(&g_rowptr[c1]);
    int rp2 = __ldg(&g_rowptr[c2]);
    float dr1 = __ldg(&g_dinv[r1]), dc1 = __ldg(&g_dinv[c1]);
    float dr2 = __ldg(&g_dinv[r2]), dc2 = __ldg(&g_dinv[c2]);
    g_csr[rp1 + p1] = make_int2(r1, __float_as_int(dr1 * w1 * dc1));
    g_csr[rp2 + p2] = make_int2(r2, __float_as_int(dr2 * w2 * dc2));
}

// ---------------- GEMM 128x128 (FFMA2) ----------------
__global__ void k_gemm128(const float* __restrict__ X, const float* __restrict__ W,
                          float* __restrict__ H, int M) {
    extern __shared__ float smdyn[];
    float* sW = smdyn;
    float* sX = smdyn + 128 * 128;
    const int tid = threadIdx.x;

    float4* sW4 = (float4*)sW;
    const float4* W4 = (const float4*)W;
    #pragma unroll
    for (int i = 0; i < 16; ++i) sW4[tid + 256 * i] = W4[tid + 256 * i];

    const int row0 = blockIdx.x * 64;
    float4* sX4 = (float4*)sX;
    #pragma unroll
    for (int i = 0; i < 8; ++i) {
        int idx = tid + 256 * i;
        int r = idx >> 5, c = idx & 31;
        int gr = min(row0 + r, M - 1);
        sX4[idx] = ((const float4*)(X + (size_t)gr * 128))[c];
    }
    __syncthreads();

    const int tx = tid & 15;
    const int ty = tid >> 4;

    unsigned long long acc[4][4];
    #pragma unroll
    for (int r = 0; r < 4; ++r)
        #pragma unroll
        for (int c = 0; c < 4; ++c) acc[r][c] = 0ull;

    const float* xbase = sX + (4 * ty) * 128;
    const float* wbase = sW + 8 * tx;

    #pragma unroll 4
    for (int k4 = 0; k4 < 32; ++k4) {
        float4 xr0 = *(const float4*)(xbase + 0 * 128 + 4 * k4);
        float4 xr1 = *(const float4*)(xbase + 1 * 128 + 4 * k4);
        float4 xr2 = *(const float4*)(xbase + 2 * 128 + 4 * k4);
        float4 xr3 = *(const float4*)(xbase + 3 * 128 + 4 * k4);
        #pragma unroll
        for (int kk = 0; kk < 4; ++kk) {
            const float* wrow = wbase + (4 * k4 + kk) * 128;
            ulonglong2 w01 = *(const ulonglong2*)(wrow);
            ulonglong2 w23 = *(const ulonglong2*)(wrow + 4);
            float x0 = (&xr0.x)[kk];
            float x1 = (&xr1.x)[kk];
            float x2 = (&xr2.x)[kk];
            float x3 = (&xr3.x)[kk];
            unsigned long long p0 = pack2(x0, x0);
            unsigned long long p1 = pack2(x1, x1);
            unsigned long long p2 = pack2(x2, x2);
            unsigned long long p3 = pack2(x3, x3);
            ffma2(acc[0][0], p0, w01.x); ffma2(acc[0][1], p0, w01.y);
            ffma2(acc[0][2], p0, w23.x); ffma2(acc[0][3], p0, w23.y);
            ffma2(acc[1][0], p1, w01.x); ffma2(acc[1][1], p1, w01.y);
            ffma2(acc[1][2], p1, w23.x); ffma2(acc[1][3], p1, w23.y);
            ffma2(acc[2][0], p2, w01.x); ffma2(acc[2][1], p2, w01.y);
            ffma2(acc[2][2], p2, w23.x); ffma2(acc[2][3], p2, w23.y);
            ffma2(acc[3][0], p3, w01.x); ffma2(acc[3][1], p3, w01.y);
            ffma2(acc[3][2], p3, w23.x); ffma2(acc[3][3], p3, w23.y);
        }
    }

    const int cg = 8 * tx;
    #pragma unroll
    for (int r = 0; r < 4; ++r) {
        int gr = row0 + 4 * ty + r;
        if (gr < M) {
            float2 q0 = unpack2(acc[r][0]);
            float2 q1 = unpack2(acc[r][1]);
            float2 q2 = unpack2(acc[r][2]);
            float2 q3 = unpack2(acc[r][3]);
            float4* dst = (float4*)(H + (size_t)gr * 128 + cg);
            dst[0] = make_float4(q0.x, q0.y, q1.x, q1.y);
            dst[1] = make_float4(q2.x, q2.y, q3.x, q3.y);
        }
    }
}

// ---------------- GEMM small-N (layer 3, N=40) ----------------
__global__ void k_gemm_small(const float* __restrict__ X, const float* __restrict__ W,
                             float* __restrict__ H, int M, int N) {
    __shared__ float sW[128 * 64];
    const int tid = threadIdx.x;
    const int sw = N;

    for (int i = tid; i < 128 * sw; i += 256) {
        int k = i / sw, c = i - k * sw;
        sW[k * 64 + c] = W[k * N + c];
    }
    __syncthreads();

    const int warp = tid >> 5;
    const int lane = tid & 31;
    const int r0 = blockIdx.x * 32 + warp * 4;
    const int myc = lane * 2;
    if (myc >= sw) return;

    const float* x0 = X + (size_t)min(r0 + 0, M - 1) * 128;
    const float* x1 = X + (size_t)min(r0 + 1, M - 1) * 128;
    const float* x2 = X + (size_t)min(r0 + 2, M - 1) * 128;
    const float* x3 = X + (size_t)min(r0 + 3, M - 1) * 128;

    float2 a0 = {0.f, 0.f}, a1 = a0, a2 = a0, a3 = a0;
    #pragma unroll 8
    for (int k = 0; k < 128; ++k) {
        float w0 = sW[k * 64 + myc];
        float w1 = sW[k * 64 + myc + 1];
        float v0 = __ldg(x0 + k), v1 = __ldg(x1 + k);
        float v2 = __ldg(x2 + k), v3 = __ldg(x3 + k);
        a0.x += v0 * w0; a0.y += v0 * w1;
        a1.x += v1 * w0; a1.y += v1 * w1;
        a2.x += v2 * w0; a2.y += v2 * w1;
        a3.x += v3 * w0; a3.y += v3 * w1;
    }

    if (r0 + 0 < M) *(float2*)(H + (size_t)(r0 + 0) * N + myc) = a0;
    if (r0 + 1 < M) *(float2*)(H + (size_t)(r0 + 1) * N + myc) = a1;
    if (r0 + 2 < M) *(float2*)(H + (size_t)(r0 + 2) * N + myc) = a2;
    if (r0 + 3 < M) *(float2*)(H + (size_t)(r0 + 3) * N + myc) = a3;
}

// ---------------- pull aggregation: single-wave grid, x8+x4 unroll ----------------
template <int F, bool RELU, bool FINAL>
__global__ void k_aggregate(const float* __restrict__ H,
                            const float* __restrict__ bias,
                            float* __restrict__ out) {
    const int gw = (blockIdx.x * blockDim.x + threadIdx.x) >> 5;
    const int lane = threadIdx.x & 31;
    const int nwarps = (gridDim.x * blockDim.x) >> 5;
    const int c4 = lane * 4;
    const bool active = (F == 128) || (c4 < F);

    for (int i = gw; i < N_NODES; i += nwarps) {
        float di = g_dinv[i];
        float sn = di * di;
        float4 acc = make_float4(0.f, 0.f, 0.f, 0.f);
        if (active) {
            float4 h = *(const float4*)(H + (size_t)i * F + c4);
            acc.x = sn * h.x; acc.y = sn * h.y; acc.z = sn * h.z; acc.w = sn * h.w;
        }
        const int beg = g_rowptr[i];
        const int end = g_rowptr[i + 1];
        for (int e = beg; e < end; e += 32) {
            int nb = end - e; if (nb > 32) nb = 32;
            int s = 0; float w = 0.f;
            if (lane < nb) {
                int2 sv = __ldg(&g_csr[e + lane]);
                s = sv.x;
                w = __int_as_float(sv.y);
            }
            int j = 0;
            for (; j + 8 <= nb; j += 8) {
                int   si[8]; float wi[8];
                #pragma unroll
                for (int q = 0; q < 8; ++q) {
                    si[q] = __shfl_sync(0xffffffffu, s, j + q);
                    wi[q] = __shfl_sync(0xffffffffu, w, j + q);
                }
                if (active) {
                    float4 hv[8];
                    #pragma unroll
                    for (int q = 0; q < 8; ++q)
                        hv[q] = __ldg((const float4*)(H + (size_t)si[q] * F + c4));
                    #pragma unroll
                    for (int q = 0; q < 8; ++q) {
                        acc.x += wi[q] * hv[q].x; acc.y += wi[q] * hv[q].y;
                        acc.z += wi[q] * hv[q].z; acc.w += wi[q] * hv[q].w;
                    }
                }
            }
            for (; j + 4 <= nb; j += 4) {
                int   s0 = __shfl_sync(0xffffffffu, s, j + 0);
                int   s1 = __shfl_sync(0xffffffffu, s, j + 1);
                int   s2 = __shfl_sync(0xffffffffu, s, j + 2);
                int   s3 = __shfl_sync(0xffffffffu, s, j + 3);
                float w0 = __shfl_sync(0xffffffffu, w, j + 0);
                float w1 = __shfl_sync(0xffffffffu, w, j + 1);
                float w2 = __shfl_sync(0xffffffffu, w, j + 2);
                float w3 = __shfl_sync(0xffffffffu, w, j + 3);
                if (active) {
                    float4 h0 = __ldg((const float4*)(H + (size_t)s0 * F + c4));
                    float4 h1 = __ldg((const float4*)(H + (size_t)s1 * F + c4));
                    float4 h2 = __ldg((const float4*)(H + (size_t)s2 * F + c4));
                    float4 h3 = __ldg((const float4*)(H + (size_t)s3 * F + c4));
                    acc.x += w0 * h0.x; acc.y += w0 * h0.y; acc.z += w0 * h0.z; acc.w += w0 * h0.w;
                    acc.x += w1 * h1.x; acc.y += w1 * h1.y; acc.z += w1 * h1.z; acc.w += w1 * h1.w;
                    acc.x += w2 * h2.x; acc.y += w2 * h2.y; acc.z += w2 * h2.z; acc.w += w2 * h2.w;
                    acc.x += w3 * h3.x; acc.y += w3 * h3.y; acc.z += w3 * h3.z; acc.w += w3 * h3.w;
                }
            }
            for (; j < nb; ++j) {
                int   sj = __shfl_sync(0xffffffffu, s, j);
                float wj = __shfl_sync(0xffffffffu, w, j);
                if (active) {
                    float4 h = __ldg((const float4*)(H + (size_t)sj * F + c4));
                    acc.x += wj * h.x; acc.y += wj * h.y;
                    acc.z += wj * h.z; acc.w += wj * h.w;
                }
            }
        }
        if (active) {
            float4 b = *(const float4*)(bias + c4);
            acc.x += b.x; acc.y += b.y; acc.z += b.z; acc.w += b.w;
            if (RELU) {
                acc.x = fmaxf(acc.x, 0.f); acc.y = fmaxf(acc.y, 0.f);
                acc.z = fmaxf(acc.z, 0.f); acc.w = fmaxf(acc.w, 0.f);
            }
            if (!FINAL) {
                *(float4*)(out + (size_t)i * F + c4) = acc;
            } else {
                if (g_mint[i]) {
                    int p = g_outpos[i];
                    *(float4*)(out + (size_t)p * F + c4) = acc;
                }
            }
        }
    }
}

// ---------------- launch ----------------
extern "C" void kernel_launch(void* const* d_in, const int* in_sizes, int n_in,
                              void* d_out, int out_size) {
    const float *x = 0, *ew = 0, *W1 = 0, *b1 = 0, *W2 = 0, *b2 = 0, *W3 = 0, *b3 = 0;
    const void* ei = 0;
    const void* mask = 0;
    for (int i = 0; i < n_in; ++i) {
        switch (in_sizes[i]) {
            case 6400000: x = (const float*)d_in[i]; break;
            case 800000:  ew = (const float*)d_in[i]; break;
            case 16384:   if (!W1) W1 = (const float*)d_in[i]; else W2 = (const float*)d_in[i]; break;
            case 5120:    W3 = (const float*)d_in[i]; break;
            case 128:     if (!b1) b1 = (const float*)d_in[i]; else b2 = (const float*)d_in[i]; break;
            case 40:      b3 = (const float*)d_in[i]; break;
            case 1600000: ei = d_in[i]; break;
            case 50000:   mask = d_in[i]; break;
            default: break;
        }
    }
    float* out = (float*)d_out;

    static cudaStream_t s2 = 0;
    static cudaEvent_t evFork = 0, evJoin = 0;
    static bool init_done = false;
    if (!init_done) {
        cudaFuncSetAttribute(k_gemm128, cudaFuncAttributeMaxDynamicSharedMemorySize,
                             (128 * 128 + 64 * 128) * sizeof(float));
        cudaStreamCreateWithFlags(&s2, cudaStreamNonBlocking);
        cudaEventCreateWithFlags(&evFork, cudaEventDisableTiming);
        cudaEventCreateWithFlags(&evJoin, cudaEventDisableTiming);
        init_done = true;
    }

    float *hA, *hB, *hC;
    cudaGetSymbolAddress((void**)&hA, g_hA);
    cudaGetSymbolAddress((void**)&hB, g_hB);
    cudaGetSymbolAddress((void**)&hC, g_hC);

    const size_t smemG = (size_t)(128 * 128 + 64 * 128) * sizeof(float);
    const int gx128 = (N_NODES + 63) / 64;
    const int gx32  = (N_NODES + 31) / 32;

    // ---- fork: GEMM L1 (independent of graph preprocessing) on side stream ----
    cudaEventRecord(evFork, 0);
    cudaStreamWaitEvent(s2, evFork, 0);
    k_gemm128<<<gx128, 256, smemG, s2>>>(x, W1, hA, N_NODES);
    cudaEventRecord(evJoin, s2);

    // ---- preprocessing chain on main stream (concurrent with GEMM L1) ----
    k_prep0<<<NB_NODE, 256>>>(mask, ei);
    k_edge_prep<<<NB_EDGE2, 256>>>(ei, ew);
    k_scan_fused<<<NB_NODE, 256>>>();
    k_scatter<<<NB_EDGE2, 256>>>();

    // ---- join, then the serial tail ----
    cudaStreamWaitEvent(0, evJoin, 0);
    k_aggregate<128, true, false><<<AGG_BLOCKS, 256>>>(hA, b1, hB);
    k_gemm128<<<gx128, 256, smemG>>>(hB, W2, hA, N_NODES);
    k_aggregate<128, true, false><<<AGG_BLOCKS, 256>>>(hA, b2, hB);
    k_gemm_small<<<gx32, 256>>>(hB, W3, hC, N_NODES, 40);
    k_aggregate<40, false, true><<<AGG_BLOCKS, 256>>>(hC, b3, out);
}

// round 17
// speedup vs baseline: 1.1087x; 1.1087x over previous
#include <cuda_runtime.h>
#include <stdint.h>

#define N_NODES 50000
#define N_EDGES 800000
#define F_HID 128
#define F_OUT 40
#define NB_NODE 196   /* ceil(50000/256) */
#define E_HALF 400000
#define NB_EDGE2 1563 /* ceil(400000/256) */

// ---------------- device scratch ----------------
__device__ __align__(16) int   g_row[N_EDGES];
__device__ __align__(16) int   g_col[N_EDGES];
__device__ __align__(16) float g_ewc[N_EDGES];
__device__ __align__(16) int   g_pos[N_EDGES];
__device__ __align__(16) float g_deg[N_NODES];
__device__ __align__(16) float g_dinv[N_NODES];
__device__ __align__(16) int   g_count[N_NODES];
__device__ __align__(16) int   g_mint[N_NODES];
__device__ __align__(16) int   g_rowptr[N_NODES + 1];
__device__ __align__(16) int   g_outpos[N_NODES];
__device__ volatile unsigned long long g_bsum[256];
__device__ __align__(16) int2  g_csr[N_EDGES];
__device__ __align__(16) float g_hA[(size_t)N_NODES * F_HID];
__device__ __align__(16) float g_hB[(size_t)N_NODES * F_HID];
__device__ __align__(16) float g_hC[(size_t)N_NODES * F_OUT];
__device__ int g_is64;

// ---------------- packed f32x2 helpers (Blackwell FFMA2) ----------------
__device__ __forceinline__ unsigned long long pack2(float lo, float hi) {
    unsigned long long r;
    asm("mov.b64 %0, {%1, %2};" : "=l"(r) : "f"(lo), "f"(hi));
    return r;
}
__device__ __forceinline__ void ffma2(unsigned long long& d,
                                      unsigned long long a,
                                      unsigned long long b) {
    asm("fma.rn.f32x2 %0, %1, %2, %0;" : "+l"(d) : "l"(a), "l"(b));
}
__device__ __forceinline__ float2 unpack2(unsigned long long v) {
    float lo, hi;
    asm("mov.b64 {%0, %1}, %2;" : "=f"(lo), "=f"(hi) : "l"(v));
    return make_float2(lo, hi);
}

// ---------------- fused init: probe + zero + mask decode ----------------
__global__ void k_prep0(const void* mask_, const void* ei_) {
    int i = blockIdx.x * blockDim.x + threadIdx.x;
    if (i == 0) {
        const long long* p = (const long long*)ei_;
        int ok = 1;
        #pragma unroll 1
        for (int k = 0; k < 64; ++k) {
            long long v = p[k];
            if (v < 0 || v >= N_NODES) { ok = 0; break; }
        }
        g_is64 = ok;
    }
    if (i < 256) g_bsum[i] = 0ull;
    if (i < N_NODES) {
        g_deg[i] = 0.0f;
        g_count[i] = 0;
        unsigned int w0 = ((const unsigned int*)mask_)[0];
        int m;
        if (w0 == 1u) m = (((const int*)mask_)[i] != 0) ? 1 : 0;
        else          m = (((const unsigned char*)mask_)[i] != 0) ? 1 : 0;
        g_mint[i] = m;
    }
}

// ---------------- edge prep: 2 edges/thread ----------------
__global__ void k_edge_prep(const void* ei_, const float* __restrict__ ew) {
    int e = blockIdx.x * blockDim.x + threadIdx.x;
    if (e >= E_HALF) return;
    const int e2 = e + E_HALF;
    int r1, c1, r2, c2;
    if (g_is64) {
        const long long* ei = (const long long*)ei_;
        long long a0 = __ldg(ei + e);
        long long a1 = __ldg(ei + N_EDGES + e);
        long long a2 = __ldg(ei + e2);
        long long a3 = __ldg(ei + N_EDGES + e2);
        r1 = (int)a0; c1 = (int)a1; r2 = (int)a2; c2 = (int)a3;
    } else {
        const int* ei = (const int*)ei_;
        int a0 = __ldg(ei + e);
        int a1 = __ldg(ei + N_EDGES + e);
        int a2 = __ldg(ei + e2);
        int a3 = __ldg(ei + N_EDGES + e2);
        r1 = a0; c1 = a1; r2 = a2; c2 = a3;
    }
    float w1 = __ldg(ew + e);
    float w2 = __ldg(ew + e2);
    r1 = min(max(r1, 0), N_NODES - 1);
    c1 = min(max(c1, 0), N_NODES - 1);
    r2 = min(max(r2, 0), N_NODES - 1);
    c2 = min(max(c2, 0), N_NODES - 1);
    g_row[e] = r1;  g_col[e] = c1;  g_ewc[e] = w1;
    g_row[e2] = r2; g_col[e2] = c2; g_ewc[e2] = w2;
    atomicAdd(&g_deg[c1], w1);
    atomicAdd(&g_deg[c2], w2);
    g_pos[e]  = atomicAdd(&g_count[c1], 1);
    g_pos[e2] = atomicAdd(&g_count[c2], 1);
}

// ---------------- single-kernel dual scan (decoupled lookback) ----------------
__global__ void k_scan_fused() {
    __shared__ int sa[256], sb[256];
    __shared__ int s_prefA, s_prefB;
    const int t = threadIdx.x;
    const int bid = blockIdx.x;
    const int i = bid * 256 + t;
    int va = (i < N_NODES) ? g_count[i] : 0;
    int vb = (i < N_NODES) ? g_mint[i] : 0;
    sa[t] = va; sb[t] = vb;
    __syncthreads();
    for (int off = 1; off < 256; off <<= 1) {
        int aa = (t >= off) ? sa[t - off] : 0;
        int ab = (t >= off) ? sb[t - off] : 0;
        __syncthreads();
        sa[t] += aa; sb[t] += ab;
        __syncthreads();
    }
    if (t == 255) {
        unsigned long long v = ((unsigned long long)(unsigned)sb[255] << 32)
                             | (unsigned)(sa[255] + 1);
        g_bsum[bid] = v;
    }
    if (t < 32) {
        int pA = 0, pB = 0;
        for (int p = t; p < bid; p += 32) {
            unsigned long long v;
            do { v = g_bsum[p]; } while ((unsigned)v == 0u);
            pA += (int)((unsigned)v) - 1;
            pB += (int)(v >> 32);
        }
        #pragma unroll
        for (int off = 16; off > 0; off >>= 1) {
            pA += __shfl_down_sync(0xffffffffu, pA, off);
            pB += __shfl_down_sync(0xffffffffu, pB, off);
        }
        if (t == 0) { s_prefA = pA; s_prefB = pB; }
    }
    __syncthreads();
    if (i < N_NODES) {
        g_rowptr[i] = s_prefA + sa[t] - va;
        g_outpos[i] = s_prefB + sb[t] - vb;
        g_dinv[i] = rsqrtf(g_deg[i] + 1.0f);
    }
    if (bid == NB_NODE - 1 && t == 255) {
        g_rowptr[N_NODES] = s_prefA + sa[255];
    }
}

// ---------------- scatter: 2 edges/thread, no atomics ----------------
__global__ void k_scatter() {
    int e = blockIdx.x * blockDim.x + threadIdx.x;
    if (e >= E_HALF) return;
    const int e2 = e + E_HALF;
    int c1 = g_col[e],  r1 = g_row[e];
    int c2 = g_col[e2], r2 = g_row[e2];
    float w1 = g_ewc[e], w2 = g_ewc[e2];
    int p1 = g_pos[e],   p2 = g_pos[e2];
    int rp1 = __ldg(&g_rowptr[c1]);
    int rp2 = __ldg(&g_rowptr[c2]);
    float dr1 = __ldg(&g_dinv[r1]), dc1 = __ldg(&g_dinv[c1]);
    float dr2 = __ldg(&g_dinv[r2]), dc2 = __ldg(&g_dinv[c2]);
    g_csr[rp1 + p1] = make_int2(r1, __float_as_int(dr1 * w1 * dc1));
    g_csr[rp2 + p2] = make_int2(r2, __float_as_int(dr2 * w2 * dc2));
}

// ---------------- GEMM 128x128 (FFMA2; layer-1, hidden behind prep) ----------------
__global__ void k_gemm128(const float* __restrict__ X, const float* __restrict__ W,
                          float* __restrict__ H, int M) {
    extern __shared__ float smdyn[];
    float* sW = smdyn;
    float* sX = smdyn + 128 * 128;
    const int tid = threadIdx.x;

    float4* sW4 = (float4*)sW;
    const float4* W4 = (const float4*)W;
    #pragma unroll
    for (int i = 0; i < 16; ++i) sW4[tid + 256 * i] = W4[tid + 256 * i];

    const int row0 = blockIdx.x * 64;
    float4* sX4 = (float4*)sX;
    #pragma unroll
    for (int i = 0; i < 8; ++i) {
        int idx = tid + 256 * i;
        int r = idx >> 5, c = idx & 31;
        int gr = min(row0 + r, M - 1);
        sX4[idx] = ((const float4*)(X + (size_t)gr * 128))[c];
    }
    __syncthreads();

    const int tx = tid & 15;
    const int ty = tid >> 4;

    unsigned long long acc[4][4];
    #pragma unroll
    for (int r = 0; r < 4; ++r)
        #pragma unroll
        for (int c = 0; c < 4; ++c) acc[r][c] = 0ull;

    const float* xbase = sX + (4 * ty) * 128;
    const float* wbase = sW + 8 * tx;

    #pragma unroll 4
    for (int k4 = 0; k4 < 32; ++k4) {
        float4 xr0 = *(const float4*)(xbase + 0 * 128 + 4 * k4);
        float4 xr1 = *(const float4*)(xbase + 1 * 128 + 4 * k4);
        float4 xr2 = *(const float4*)(xbase + 2 * 128 + 4 * k4);
        float4 xr3 = *(const float4*)(xbase + 3 * 128 + 4 * k4);
        #pragma unroll
        for (int kk = 0; kk < 4; ++kk) {
            const float* wrow = wbase + (4 * k4 + kk) * 128;
            ulonglong2 w01 = *(const ulonglong2*)(wrow);
            ulonglong2 w23 = *(const ulonglong2*)(wrow + 4);
            float x0 = (&xr0.x)[kk];
            float x1 = (&xr1.x)[kk];
            float x2 = (&xr2.x)[kk];
            float x3 = (&xr3.x)[kk];
            unsigned long long p0 = pack2(x0, x0);
            unsigned long long p1 = pack2(x1, x1);
            unsigned long long p2 = pack2(x2, x2);
            unsigned long long p3 = pack2(x3, x3);
            ffma2(acc[0][0], p0, w01.x); ffma2(acc[0][1], p0, w01.y);
            ffma2(acc[0][2], p0, w23.x); ffma2(acc[0][3], p0, w23.y);
            ffma2(acc[1][0], p1, w01.x); ffma2(acc[1][1], p1, w01.y);
            ffma2(acc[1][2], p1, w23.x); ffma2(acc[1][3], p1, w23.y);
            ffma2(acc[2][0], p2, w01.x); ffma2(acc[2][1], p2, w01.y);
            ffma2(acc[2][2], p2, w23.x); ffma2(acc[2][3], p2, w23.y);
            ffma2(acc[3][0], p3, w01.x); ffma2(acc[3][1], p3, w01.y);
            ffma2(acc[3][2], p3, w23.x); ffma2(acc[3][3], p3, w23.y);
        }
    }

    const int cg = 8 * tx;
    #pragma unroll
    for (int r = 0; r < 4; ++r) {
        int gr = row0 + 4 * ty + r;
        if (gr < M) {
            float2 q0 = unpack2(acc[r][0]);
            float2 q1 = unpack2(acc[r][1]);
            float2 q2 = unpack2(acc[r][2]);
            float2 q3 = unpack2(acc[r][3]);
            float4* dst = (float4*)(H + (size_t)gr * 128 + cg);
            dst[0] = make_float4(q0.x, q0.y, q1.x, q1.y);
            dst[1] = make_float4(q2.x, q2.y, q3.x, q3.y);
        }
    }
}

// ---------------- GEMM 128x128 via mma.sync tf32 (layer 2) ----------------
// 64x128 tile per 256-thread block; 8 warps in 4x2 grid; each warp 16x64.
// A,B staged in smem as tf32 bit patterns, row stride 132 (bank-conflict pad).
#define MMA_STRIDE 132
#define MMA_SMEM_W 0                       /* 128*132 u32 */
#define MMA_SMEM_X (128 * MMA_STRIDE)      /* 64*132 u32 */
#define MMA_SMEM_TOTAL ((128 * MMA_STRIDE + 64 * MMA_STRIDE) * 4)

__global__ void k_gemm_mma(const float* __restrict__ X, const float* __restrict__ W,
                           float* __restrict__ H, int M) {
    extern __shared__ uint32_t smu[];
    uint32_t* sW = smu + MMA_SMEM_W;
    uint32_t* sX = smu + MMA_SMEM_X;
    const int tid = threadIdx.x;
    const int row0 = blockIdx.x * 64;

    // stage W (128x128) as tf32 bits
    for (int idx = tid; idx < 128 * 128; idx += 256) {
        int k = idx >> 7, n = idx & 127;
        float v = __ldg(W + idx);
        uint32_t t;
        asm("cvt.rna.tf32.f32 %0, %1;" : "=r"(t) : "f"(v));
        sW[k * MMA_STRIDE + n] = t;
    }
    // stage X tile (64x128)
    for (int idx = tid; idx < 64 * 128; idx += 256) {
        int r = idx >> 7, c = idx & 127;
        int gr = min(row0 + r, M - 1);
        float v = __ldg(X + (size_t)gr * 128 + c);
        uint32_t t;
        asm("cvt.rna.tf32.f32 %0, %1;" : "=r"(t) : "f"(v));
        sX[r * MMA_STRIDE + c] = t;
    }
    __syncthreads();

    const int warp = tid >> 5;
    const int lane = tid & 31;
    const int g = lane >> 2;       // group 0..7
    const int tig = lane & 3;      // thread in group
    const int wr = warp & 3;       // row group: rows 16*wr..+16
    const int wc = warp >> 2;      // col group: cols 64*wc..+64
    const int mr = 16 * wr;
    const int nc = 64 * wc;

    float d[8][4];
    #pragma unroll
    for (int nt = 0; nt < 8; ++nt)
        #pragma unroll
        for (int q = 0; q < 4; ++q) d[nt][q] = 0.f;

    #pragma unroll 4
    for (int ks = 0; ks < 16; ++ks) {
        const int k0 = 8 * ks;
        uint32_t a0 = sX[(mr + g) * MMA_STRIDE + k0 + tig];
        uint32_t a1 = sX[(mr + g + 8) * MMA_STRIDE + k0 + tig];
        uint32_t a2 = sX[(mr + g) * MMA_STRIDE + k0 + tig + 4];
        uint32_t a3 = sX[(mr + g + 8) * MMA_STRIDE + k0 + tig + 4];
        const uint32_t* w0row = sW + (k0 + tig) * MMA_STRIDE;
        const uint32_t* w1row = sW + (k0 + tig + 4) * MMA_STRIDE;
        #pragma unroll
        for (int nt = 0; nt < 8; ++nt) {
            int n0 = nc + 8 * nt;
            uint32_t b0 = w0row[n0 + g];
            uint32_t b1 = w1row[n0 + g];
            asm volatile(
                "mma.sync.aligned.m16n8k8.row.col.f32.tf32.tf32.f32 "
                "{%0,%1,%2,%3}, {%4,%5,%6,%7}, {%8,%9}, {%0,%1,%2,%3};"
                : "+f"(d[nt][0]), "+f"(d[nt][1]), "+f"(d[nt][2]), "+f"(d[nt][3])
                : "r"(a0), "r"(a1), "r"(a2), "r"(a3), "r"(b0), "r"(b1));
        }
    }

    const int gr0 = row0 + mr + g;
    const int gr1 = gr0 + 8;
    #pragma unroll
    for (int nt = 0; nt < 8; ++nt) {
        int col = nc + 8 * nt + 2 * tig;
        if (gr0 < M) *(float2*)(H + (size_t)gr0 * 128 + col) = make_float2(d[nt][0], d[nt][1]);
        if (gr1 < M) *(float2*)(H + (size_t)gr1 * 128 + col) = make_float2(d[nt][2], d[nt][3]);
    }
}

// ---------------- GEMM small-N (layer 3, N=40) ----------------
__global__ void k_gemm_small(const float* __restrict__ X, const float* __restrict__ W,
                             float* __restrict__ H, int M, int N) {
    __shared__ float sW[128 * 64];
    const int tid = threadIdx.x;
    const int sw = N;

    for (int i = tid; i < 128 * sw; i += 256) {
        int k = i / sw, c = i - k * sw;
        sW[k * 64 + c] = W[k * N + c];
    }
    __syncthreads();

    const int warp = tid >> 5;
    const int lane = tid & 31;
    const int r0 = blockIdx.x * 32 + warp * 4;
    const int myc = lane * 2;
    if (myc >= sw) return;

    const float* x0 = X + (size_t)min(r0 + 0, M - 1) * 128;
    const float* x1 = X + (size_t)min(r0 + 1, M - 1) * 128;
    const float* x2 = X + (size_t)min(r0 + 2, M - 1) * 128;
    const float* x3 = X + (size_t)min(r0 + 3, M - 1) * 128;

    float2 a0 = {0.f, 0.f}, a1 = a0, a2 = a0, a3 = a0;
    #pragma unroll 8
    for (int k = 0; k < 128; ++k) {
        float w0 = sW[k * 64 + myc];
        float w1 = sW[k * 64 + myc + 1];
        float v0 = __ldg(x0 + k), v1 = __ldg(x1 + k);
        float v2 = __ldg(x2 + k), v3 = __ldg(x3 + k);
        a0.x += v0 * w0; a0.y += v0 * w1;
        a1.x += v1 * w0; a1.y += v1 * w1;
        a2.x += v2 * w0; a2.y += v2 * w1;
        a3.x += v3 * w0; a3.y += v3 * w1;
    }

    if (r0 + 0 < M) *(float2*)(H + (size_t)(r0 + 0) * N + myc) = a0;
    if (r0 + 1 < M) *(float2*)(H + (size_t)(r0 + 1) * N + myc) = a1;
    if (r0 + 2 < M) *(float2*)(H + (size_t)(r0 + 2) * N + myc) = a2;
    if (r0 + 3 < M) *(float2*)(H + (size_t)(r0 + 3) * N + myc) = a3;
}

// ---------------- pull aggregation (warp/node, float4, x4 unroll) ----------------
template <int F, bool RELU, bool FINAL>
__global__ void k_aggregate(const float* __restrict__ H,
                            const float* __restrict__ bias,
                            float* __restrict__ out) {
    const int gw = (blockIdx.x * blockDim.x + threadIdx.x) >> 5;
    const int lane = threadIdx.x & 31;
    const int nwarps = (gridDim.x * blockDim.x) >> 5;
    const int c4 = lane * 4;
    const bool active = (F == 128) || (c4 < F);

    for (int i = gw; i < N_NODES; i += nwarps) {
        float di = g_dinv[i];
        float sn = di * di;
        float4 acc = make_float4(0.f, 0.f, 0.f, 0.f);
        if (active) {
            float4 h = *(const float4*)(H + (size_t)i * F + c4);
            acc.x = sn * h.x; acc.y = sn * h.y; acc.z = sn * h.z; acc.w = sn * h.w;
        }
        const int beg = g_rowptr[i];
        const int end = g_rowptr[i + 1];
        for (int e = beg; e < end; e += 32) {
            int nb = end - e; if (nb > 32) nb = 32;
            int s = 0; float w = 0.f;
            if (lane < nb) {
                int2 sv = __ldg(&g_csr[e + lane]);
                s = sv.x;
                w = __int_as_float(sv.y);
            }
            int j = 0;
            for (; j + 4 <= nb; j += 4) {
                int   s0 = __shfl_sync(0xffffffffu, s, j + 0);
                int   s1 = __shfl_sync(0xffffffffu, s, j + 1);
                int   s2 = __shfl_sync(0xffffffffu, s, j + 2);
                int   s3 = __shfl_sync(0xffffffffu, s, j + 3);
                float w0 = __shfl_sync(0xffffffffu, w, j + 0);
                float w1 = __shfl_sync(0xffffffffu, w, j + 1);
                float w2 = __shfl_sync(0xffffffffu, w, j + 2);
                float w3 = __shfl_sync(0xffffffffu, w, j + 3);
                if (active) {
                    float4 h0 = __ldg((const float4*)(H + (size_t)s0 * F + c4));
                    float4 h1 = __ldg((const float4*)(H + (size_t)s1 * F + c4));
                    float4 h2 = __ldg((const float4*)(H + (size_t)s2 * F + c4));
                    float4 h3 = __ldg((const float4*)(H + (size_t)s3 * F + c4));
                    acc.x += w0 * h0.x; acc.y += w0 * h0.y; acc.z += w0 * h0.z; acc.w += w0 * h0.w;
                    acc.x += w1 * h1.x; acc.y += w1 * h1.y; acc.z += w1 * h1.z; acc.w += w1 * h1.w;
                    acc.x += w2 * h2.x; acc.y += w2 * h2.y; acc.z += w2 * h2.z; acc.w += w2 * h2.w;
                    acc.x += w3 * h3.x; acc.y += w3 * h3.y; acc.z += w3 * h3.z; acc.w += w3 * h3.w;
                }
            }
            for (; j < nb; ++j) {
                int   sj = __shfl_sync(0xffffffffu, s, j);
                float wj = __shfl_sync(0xffffffffu, w, j);
                if (active) {
                    float4 h = __ldg((const float4*)(H + (size_t)sj * F + c4));
                    acc.x += wj * h.x; acc.y += wj * h.y;
                    acc.z += wj * h.z; acc.w += wj * h.w;
                }
            }
        }
        if (active) {
            float4 b = *(const float4*)(bias + c4);
            acc.x += b.x; acc.y += b.y; acc.z += b.z; acc.w += b.w;
            if (RELU) {
                acc.x = fmaxf(acc.x, 0.f); acc.y = fmaxf(acc.y, 0.f);
                acc.z = fmaxf(acc.z, 0.f); acc.w = fmaxf(acc.w, 0.f);
            }
            if (!FINAL) {
                *(float4*)(out + (size_t)i * F + c4) = acc;
            } else {
                if (g_mint[i]) {
                    int p = g_outpos[i];
                    *(float4*)(out + (size_t)p * F + c4) = acc;
                }
            }
        }
    }
}

// ---------------- launch ----------------
extern "C" void kernel_launch(void* const* d_in, const int* in_sizes, int n_in,
                              void* d_out, int out_size) {
    const float *x = 0, *ew = 0, *W1 = 0, *b1 = 0, *W2 = 0, *b2 = 0, *W3 = 0, *b3 = 0;
    const void* ei = 0;
    const void* mask = 0;
    for (int i = 0; i < n_in; ++i) {
        switch (in_sizes[i]) {
            case 6400000: x = (const float*)d_in[i]; break;
            case 800000:  ew = (const float*)d_in[i]; break;
            case 16384:   if (!W1) W1 = (const float*)d_in[i]; else W2 = (const float*)d_in[i]; break;
            case 5120:    W3 = (const float*)d_in[i]; break;
            case 128:     if (!b1) b1 = (const float*)d_in[i]; else b2 = (const float*)d_in[i]; break;
            case 40:      b3 = (const float*)d_in[i]; break;
            case 1600000: ei = d_in[i]; break;
            case 50000:   mask = d_in[i]; break;
            default: break;
        }
    }
    float* out = (float*)d_out;

    static cudaStream_t s2 = 0;
    static cudaEvent_t evFork = 0, evJoin = 0;
    static bool init_done = false;
    if (!init_done) {
        cudaFuncSetAttribute(k_gemm128, cudaFuncAttributeMaxDynamicSharedMemorySize,
                             (128 * 128 + 64 * 128) * sizeof(float));
        cudaFuncSetAttribute(k_gemm_mma, cudaFuncAttributeMaxDynamicSharedMemorySize,
                             MMA_SMEM_TOTAL);
        cudaStreamCreateWithFlags(&s2, cudaStreamNonBlocking);
        cudaEventCreateWithFlags(&evFork, cudaEventDisableTiming);
        cudaEventCreateWithFlags(&evJoin, cudaEventDisableTiming);
        init_done = true;
    }

    float *hA, *hB, *hC;
    cudaGetSymbolAddress((void**)&hA, g_hA);
    cudaGetSymbolAddress((void**)&hB, g_hB);
    cudaGetSymbolAddress((void**)&hC, g_hC);

    const size_t smemG = (size_t)(128 * 128 + 64 * 128) * sizeof(float);
    const int gx128 = (N_NODES + 63) / 64;
    const int gx32  = (N_NODES + 31) / 32;
    const int agg_blocks = (N_NODES + 7) / 8;

    // ---- fork: GEMM L1 (independent of graph preprocessing) on side stream ----
    cudaEventRecord(evFork, 0);
    cudaStreamWaitEvent(s2, evFork, 0);
    k_gemm128<<<gx128, 256, smemG, s2>>>(x, W1, hA, N_NODES);
    cudaEventRecord(evJoin, s2);

    // ---- preprocessing chain on main stream (concurrent with GEMM L1) ----
    k_prep0<<<NB_NODE, 256>>>(mask, ei);
    k_edge_prep<<<NB_EDGE2, 256>>>(ei, ew);
    k_scan_fused<<<NB_NODE, 256>>>();
    k_scatter<<<NB_EDGE2, 256>>>();

    // ---- join, then the serial tail (layer-2 GEMM on mma.sync tf32) ----
    cudaStreamWaitEvent(0, evJoin, 0);
    k_aggregate<128, true, false><<<agg_blocks, 256>>>(hA, b1, hB);
    k_gemm_mma<<<gx128, 256, MMA_SMEM_TOTAL>>>(hB, W2, hA, N_NODES);
    k_aggregate<128, true, false><<<agg_blocks, 256>>>(hA, b2, hB);
    k_gemm_small<<<gx32, 256>>>(hB, W3, hC, N_NODES, 40);
    k_aggregate<40, false, true><<<agg_blocks, 256>>>(hC, b3, out);
}